// round 8
// baseline (speedup 1.0000x reference)
#include <cuda_runtime.h>
#include <cuda_bf16.h>
#include <cstdint>
#include <math.h>

// Problem dims
#define BB   256
#define TT   200
#define DD   311
#define UU   256
#define G3   768          // 3*U
#define NOUT 19
#define BT   (BB*TT)      // 51200

typedef unsigned long long u64;

// ---------------- packed f32x2 helpers (Blackwell PTX) ---------------------
__device__ __forceinline__ u64 splat2(float v) {
    u64 r; unsigned u = __float_as_uint(v);
    asm("mov.b64 %0, {%1, %1};" : "=l"(r) : "r"(u));
    return r;
}
__device__ __forceinline__ void ffma2(u64& d, u64 a, u64 b) {
    asm("fma.rn.f32x2 %0, %1, %2, %0;" : "+l"(d) : "l"(a), "l"(b));
}
__device__ __forceinline__ float lo2(u64 v) {
    return __uint_as_float((unsigned)(v & 0xffffffffull));
}
__device__ __forceinline__ float hi2(u64 v) {
    return __uint_as_float((unsigned)(v >> 32));
}

// ---------------- scratch (device globals; no cudaMalloc allowed) ----------
__device__ float g_xp[2][(size_t)BT * G3];   // input projections, per direction
__device__ float g_y [2][(size_t)BT * UU];   // hidden sequences
__device__ int   g_mask[BT];
__device__ float g_rkp2[2 * 8 * 96 * 256];   // rk col-major [dir][cc][col][k]
__device__ float g_b1p[2 * 8 * 96];          // recurrent bias per (dir, cc)

__device__ __forceinline__ float sigmoidf_(float v) {
    return 1.0f / (1.0f + expf(-v));
}

// ---------------- mask: mask[b,t] = any(x[b,t,:] != 0) ---------------------
__global__ __launch_bounds__(256) void mask_kernel(const float* __restrict__ x) {
    int warp = (blockIdx.x * blockDim.x + threadIdx.x) >> 5;
    int lane = threadIdx.x & 31;
    if (warp >= BT) return;
    const float* row = x + (size_t)warp * DD;
    int any = 0;
    for (int i = lane; i < DD; i += 32) any |= (row[i] != 0.0f);
    unsigned b = __ballot_sync(0xffffffffu, any);
    if (lane == 0) g_mask[warp] = (b != 0u);
}

// ---------------- weight pre-pack: col-major per (dir, unit-chunk) ---------
// local col c in [0,96): global col (c/32)*256 + cc*32 + (c%32); k contiguous.
__global__ __launch_bounds__(256) void pack_kernel(
    const float* __restrict__ rk_f, const float* __restrict__ rk_b,
    const float* __restrict__ b_f,  const float* __restrict__ b_b)
{
    int i = blockIdx.x * blockDim.x + threadIdx.x;
    const int total = 2 * 8 * 96 * 256;
    if (i < total) {
        int k     = i & 255;
        int rest  = i >> 8;
        int c     = rest % 96;
        int slice = rest / 96;          // 0..15
        int cc    = slice & 7;
        int dir   = slice >> 3;
        const float* rk = dir ? rk_b : rk_f;
        g_rkp2[i] = rk[(size_t)k * G3 + (c >> 5) * UU + cc * 32 + (c & 31)];
    }
    if (i < 2 * 8 * 96) {
        int c   = i % 96;
        int cc  = (i / 96) & 7;
        int dir = i / (96 * 8);
        const float* b = dir ? b_b : b_f;
        g_b1p[i] = b[G3 + (c >> 5) * UU + cc * 32 + (c & 31)];
    }
}

// ---------------- phase 1: xp[m,n] = sum_k x[m,k]*W[k,n] + b0[n] -----------
// M=51200, K=311, N=768.  128x128x8 tile, 256 thr, 8x8 per-thread (f32x2).
__global__ __launch_bounds__(256) void proj_kernel(
    const float* __restrict__ x,
    const float* __restrict__ k_f, const float* __restrict__ b_f,
    const float* __restrict__ k_b, const float* __restrict__ b_b)
{
    __shared__ float As[8 * 132];
    __shared__ float Bs[8 * 132];

    const int dir = blockIdx.z;
    const float* W    = dir ? k_b : k_f;
    const float* bias = dir ? b_b : b_f;       // row 0 = input bias
    float* xp = g_xp[dir];

    const int m0 = blockIdx.y * 128;
    const int n0 = blockIdx.x * 128;
    const int tid = threadIdx.x;
    const int tx = tid & 15;
    const int ty = tid >> 4;

    const int lxm = tid >> 1;            // 0..127
    const int lxk = (tid & 1) * 4;       // 0 or 4
    const int lbk = tid >> 5;            // 0..7
    const int lbn = (tid & 31) * 4;      // 0..124

    u64 acc2[8][4];
#pragma unroll
    for (int i = 0; i < 8; i++)
#pragma unroll
        for (int j = 0; j < 4; j++) acc2[i][j] = 0ull;

    for (int k0 = 0; k0 < DD; k0 += 8) {
#pragma unroll
        for (int j = 0; j < 4; j++) {
            int k = k0 + lxk + j;
            As[(lxk + j) * 132 + lxm] =
                (k < DD) ? __ldg(&x[(size_t)(m0 + lxm) * DD + k]) : 0.0f;
        }
        if (k0 + lbk < DD) {
            float4 v = *(const float4*)&W[(size_t)(k0 + lbk) * G3 + n0 + lbn];
            *(float4*)&Bs[lbk * 132 + lbn] = v;
        } else {
            *(float4*)&Bs[lbk * 132 + lbn] = make_float4(0.f, 0.f, 0.f, 0.f);
        }
        __syncthreads();

#pragma unroll
        for (int kk = 0; kk < 8; kk++) {
            float4 a0 = *(float4*)&As[kk * 132 + ty * 4];
            float4 a1 = *(float4*)&As[kk * 132 + 64 + ty * 4];
            const u64* bp0 = (const u64*)&Bs[kk * 132 + tx * 4];
            const u64* bp1 = (const u64*)&Bs[kk * 132 + 64 + tx * 4];
            u64 bv[4] = {bp0[0], bp0[1], bp1[0], bp1[1]};
            float av[8] = {a0.x, a0.y, a0.z, a0.w, a1.x, a1.y, a1.z, a1.w};
#pragma unroll
            for (int i = 0; i < 8; i++) {
                u64 asp = splat2(av[i]);
#pragma unroll
                for (int j = 0; j < 4; j++) ffma2(acc2[i][j], asp, bv[j]);
            }
        }
        __syncthreads();
    }

#pragma unroll
    for (int i = 0; i < 8; i++) {
        int row = m0 + ((i < 4) ? (ty * 4 + i) : (64 + ty * 4 + i - 4));
        float* o = &xp[(size_t)row * G3 + n0];
#pragma unroll
        for (int jh = 0; jh < 2; jh++) {
            int c0 = jh * 64 + tx * 4;
            float4 v;
            v.x = lo2(acc2[i][jh * 2 + 0]) + __ldg(&bias[n0 + c0 + 0]);
            v.y = hi2(acc2[i][jh * 2 + 0]) + __ldg(&bias[n0 + c0 + 1]);
            v.z = lo2(acc2[i][jh * 2 + 1]) + __ldg(&bias[n0 + c0 + 2]);
            v.w = hi2(acc2[i][jh * 2 + 1]) + __ldg(&bias[n0 + c0 + 3]);
            *(float4*)&o[c0] = v;
        }
    }
}

// ---------------- phase 2: persistent cluster scan -------------------------
// grid (8, 16), cluster (8,1,1): blockIdx.x = cc (unit chunk / cluster rank),
// blockIdx.y = dir*8 + bg. Each cluster owns 32 batch rows of one direction
// and runs ALL 200 steps; per-step h exchange via g_y ordered by cluster
// barriers. Deadlock-free: co-residency within a cluster is HW-guaranteed,
// and the 16 clusters are mutually independent.
// GEMM: rk col-major in smem, k-paired f32x2 (no splats).
#define KS2 264          // rs2 k-stride (256 + 8 pad)
#define HSK 264          // hs  k-stride
#define SCAN_SMEM_FLOATS (96 * KS2 + 32 * HSK + 32 * 100 + 96 + 32)
#define SCAN_SMEM_BYTES  (SCAN_SMEM_FLOATS * 4)

__global__ __launch_bounds__(256, 1) __cluster_dims__(8, 1, 1)
void scan_persist_kernel()
{
    extern __shared__ float sm[];
    float* rs2  = sm;                     // [96][264] rk slice, col-major
    float* hs   = rs2 + 96 * KS2;         // [32][264] h_prev
    float* recs = hs + 32 * HSK;          // [32][100] rec + b1
    float* b1s  = recs + 32 * 100;        // [96]
    int*   mkv  = (int*)(b1s + 96);       // [32]

    const int tid = threadIdx.x;
    const int cc  = blockIdx.x;           // 0..7
    const int grp = blockIdx.y;           // 0..15
    const int bg  = grp & 7;
    const int dir = grp >> 3;
    const int u0  = cc * 32;
    const int b0  = bg * 32;

    float*       y  = g_y[dir];
    const float* xp = g_xp[dir];

    // ---- one-time smem fill ----
    {
        const float4* src =
            (const float4*)(g_rkp2 + (size_t)(dir * 8 + cc) * 96 * 256);
        for (int i = tid; i < 96 * 64; i += 256) {
            int c = i >> 6, q = i & 63;
            *(float4*)&rs2[c * KS2 + 4 * q] = src[i];
        }
    }
    if (tid < 96) b1s[tid] = g_b1p[(dir * 8 + cc) * 96 + tid];
    for (int i = tid; i < 32 * HSK; i += 256) hs[i] = 0.0f;   // h0 = 0
    __syncthreads();

    const int rt = tid & 15;          // 0..15 -> rows {rt, rt+16}
    const int ct = tid >> 4;          // 0..15 -> cols 6ct..6ct+5

    const float* h0p = &hs[rt * HSK];
    const float* h1p = &hs[(rt + 16) * HSK];
    const float* wp  = &rs2[(6 * ct) * KS2];

    for (int s = 0; s < TT; s++) {
        const int t = dir ? (TT - 1 - s) : s;

        if (s > 0) {
            const int tp = dir ? (t + 1) : (t - 1);
#pragma unroll
            for (int i = 0; i < 8; i++) {        // 32 rows x 64 float4
                int idx = tid + 256 * i;
                int row = idx >> 6, q = idx & 63;
                *(float4*)&hs[row * HSK + 4 * q] =
                    *(const float4*)&y[((size_t)(b0 + row) * TT + tp) * UU + 4 * q];
            }
        }
        if (tid < 32) mkv[tid] = g_mask[(b0 + tid) * TT + t];
        __syncthreads();

        // ---- GEMM 32x96x256, k-paired f32x2 ----
        u64 acc[2][6];
#pragma unroll
        for (int i = 0; i < 2; i++)
#pragma unroll
            for (int j = 0; j < 6; j++) acc[i][j] = 0ull;

#pragma unroll 2
        for (int k0 = 0; k0 < 256; k0 += 4) {
            ulonglong2 ha = *(const ulonglong2*)(h0p + k0);
            ulonglong2 hb = *(const ulonglong2*)(h1p + k0);
#pragma unroll
            for (int j = 0; j < 6; j++) {
                ulonglong2 w = *(const ulonglong2*)(wp + j * KS2 + k0);
                ffma2(acc[0][j], ha.x, w.x);
                ffma2(acc[0][j], ha.y, w.y);
                ffma2(acc[1][j], hb.x, w.x);
                ffma2(acc[1][j], hb.y, w.y);
            }
        }

        // ---- reduce pairs, + recurrent bias, exchange via smem ----
#pragma unroll
        for (int i = 0; i < 2; i++) {
            int row = rt + 16 * i;
#pragma unroll
            for (int j = 0; j < 6; j++)
                recs[row * 100 + 6 * ct + j] =
                    lo2(acc[i][j]) + hi2(acc[i][j]) + b1s[6 * ct + j];
        }
        __syncthreads();

        // ---- gates: 4 (row, unit) items per thread ----
#pragma unroll
        for (int it = 0; it < 4; it++) {
            int i = tid + 256 * it;
            int row = i >> 5, u = i & 31;
            float rz = recs[row * 100 + u];
            float rr = recs[row * 100 + 32 + u];
            float rh = recs[row * 100 + 64 + u];
            size_t base = ((size_t)(b0 + row) * TT + t) * G3 + u0 + u;
            float xz = xp[base];
            float xr = xp[base + UU];
            float xh = xp[base + 2 * UU];
            float hp = hs[row * HSK + u0 + u];
            float z  = sigmoidf_(xz + rz);
            float r  = sigmoidf_(xr + rr);
            float hh = tanhf(xh + r * rh);
            float hn = z * hp + (1.0f - z) * hh;
            if (!mkv[row]) hn = hp;
            y[((size_t)(b0 + row) * TT + t) * UU + u0 + u] = hn;
        }

        // ---- publish y[t] to the cluster, then proceed ----
        __threadfence();
        asm volatile("barrier.cluster.arrive.aligned;" ::: "memory");
        asm volatile("barrier.cluster.wait.aligned;" ::: "memory");
    }
}

// ---------------- phase 3: dense + softmax ---------------------------------
__global__ __launch_bounds__(256) void dense_kernel(
    const float* __restrict__ w_d, const float* __restrict__ b_d,
    float* __restrict__ out)
{
    __shared__ float ws[2 * UU * NOUT];   // 512*19
    __shared__ float bs[NOUT];
    for (int i = threadIdx.x; i < 2 * UU * NOUT; i += 256) ws[i] = w_d[i];
    if (threadIdx.x < NOUT) bs[threadIdx.x] = b_d[threadIdx.x];
    __syncthreads();

    int warp = threadIdx.x >> 5, lane = threadIdx.x & 31;
    int row = blockIdx.x * 8 + warp;               // 6400 * 8 = 51200 exact
    const float* hf = g_y[0] + (size_t)row * UU;
    const float* hb = g_y[1] + (size_t)row * UU;

    float acc[NOUT];
#pragma unroll
    for (int o = 0; o < NOUT; o++) acc[o] = 0.0f;

    for (int j = lane; j < UU; j += 32) {
        float a = hf[j];
        const float* w = &ws[j * NOUT];
#pragma unroll
        for (int o = 0; o < NOUT; o++) acc[o] += a * w[o];
        float b = hb[j];
        const float* w2 = &ws[(UU + j) * NOUT];
#pragma unroll
        for (int o = 0; o < NOUT; o++) acc[o] += b * w2[o];
    }
#pragma unroll
    for (int off = 16; off > 0; off >>= 1)
#pragma unroll
        for (int o = 0; o < NOUT; o++)
            acc[o] += __shfl_xor_sync(0xffffffffu, acc[o], off);

#pragma unroll
    for (int o = 0; o < NOUT; o++) acc[o] += bs[o];
    float m = acc[0];
#pragma unroll
    for (int o = 1; o < NOUT; o++) m = fmaxf(m, acc[o]);
    float sum = 0.0f;
#pragma unroll
    for (int o = 0; o < NOUT; o++) { acc[o] = expf(acc[o] - m); sum += acc[o]; }
    float inv = 1.0f / sum;

    if (lane < NOUT) {
        float v = 0.0f;
#pragma unroll
        for (int o = 0; o < NOUT; o++) if (lane == o) v = acc[o];
        out[(size_t)row * NOUT + lane] = v * inv;
    }
}

// ---------------- launch ----------------------------------------------------
extern "C" void kernel_launch(void* const* d_in, const int* in_sizes, int n_in,
                              void* d_out, int out_size)
{
    const float* x    = (const float*)d_in[0];
    const float* k_f  = (const float*)d_in[1];
    const float* rk_f = (const float*)d_in[2];
    const float* b_f  = (const float*)d_in[3];
    const float* k_b  = (const float*)d_in[4];
    const float* rk_b = (const float*)d_in[5];
    const float* b_b  = (const float*)d_in[6];
    const float* w_d  = (const float*)d_in[7];
    const float* b_d  = (const float*)d_in[8];
    float* out = (float*)d_out;

    // mask + weight pack + input projections
    mask_kernel<<<BT / 8, 256>>>(x);
    pack_kernel<<<(2 * 8 * 96 * 256) / 256, 256>>>(rk_f, rk_b, b_f, b_b);
    dim3 pg(G3 / 128, BT / 128, 2);
    proj_kernel<<<pg, 256>>>(x, k_f, b_f, k_b, b_b);

    // persistent cluster scan (16 independent 8-CTA clusters, 200 steps)
    cudaFuncSetAttribute(scan_persist_kernel,
                         cudaFuncAttributeMaxDynamicSharedMemorySize,
                         SCAN_SMEM_BYTES);
    dim3 sg(8, 16, 1);
    scan_persist_kernel<<<sg, 256, SCAN_SMEM_BYTES>>>();

    // dense + softmax
    dense_kernel<<<BT / 8, 256>>>(w_d, b_d, out);
}

// round 9
// speedup vs baseline: 1.5959x; 1.5959x over previous
#include <cuda_runtime.h>
#include <cuda_bf16.h>
#include <cstdint>
#include <math.h>

// Problem dims
#define BB   256
#define TT   200
#define DD   311
#define UU   256
#define G3   768          // 3*U
#define NOUT 19
#define BT   (BB*TT)      // 51200

typedef unsigned long long u64;

// ---------------- packed f32x2 helpers (Blackwell PTX) ---------------------
__device__ __forceinline__ u64 splat2(float v) {
    u64 r; unsigned u = __float_as_uint(v);
    asm("mov.b64 %0, {%1, %1};" : "=l"(r) : "r"(u));
    return r;
}
__device__ __forceinline__ void ffma2(u64& d, u64 a, u64 b) {
    asm("fma.rn.f32x2 %0, %1, %2, %0;" : "+l"(d) : "l"(a), "l"(b));
}
__device__ __forceinline__ float lo2(u64 v) {
    return __uint_as_float((unsigned)(v & 0xffffffffull));
}
__device__ __forceinline__ float hi2(u64 v) {
    return __uint_as_float((unsigned)(v >> 32));
}

// ---------------- scratch (device globals; no cudaMalloc allowed) ----------
__device__ float g_xp[2][(size_t)BT * G3];   // input projections, per direction
__device__ float g_y [2][(size_t)BT * UU];   // hidden sequences
__device__ int   g_mask[BT];
__device__ float g_rkp3[2 * 16 * 48 * 256];  // rk col-major [dir][cc16][col48][k]
__device__ float g_b1p3[2 * 16 * 48];        // recurrent bias, same packing

__device__ __forceinline__ float sigmoidf_(float v) {
    return 1.0f / (1.0f + expf(-v));
}

// ---------------- mask: mask[b,t] = any(x[b,t,:] != 0) ---------------------
__global__ __launch_bounds__(256) void mask_kernel(const float* __restrict__ x) {
    int warp = (blockIdx.x * blockDim.x + threadIdx.x) >> 5;
    int lane = threadIdx.x & 31;
    if (warp >= BT) return;
    const float* row = x + (size_t)warp * DD;
    int any = 0;
    for (int i = lane; i < DD; i += 32) any |= (row[i] != 0.0f);
    unsigned b = __ballot_sync(0xffffffffu, any);
    if (lane == 0) g_mask[warp] = (b != 0u);
}

// ---------------- weight pre-pack: col-major per (dir, 16-unit chunk) ------
// local col c in [0,48): global col (c/16)*256 + cc*16 + (c%16); k contiguous.
__global__ __launch_bounds__(256) void pack_kernel(
    const float* __restrict__ rk_f, const float* __restrict__ rk_b,
    const float* __restrict__ b_f,  const float* __restrict__ b_b)
{
    int i = blockIdx.x * blockDim.x + threadIdx.x;
    const int total = 2 * 16 * 48 * 256;
    if (i < total) {
        int k     = i & 255;
        int rest  = i >> 8;
        int c     = rest % 48;
        int slice = rest / 48;          // 0..31
        int cc    = slice & 15;
        int dir   = slice >> 4;
        const float* rk = dir ? rk_b : rk_f;
        g_rkp3[i] = rk[(size_t)k * G3 + (c >> 4) * UU + cc * 16 + (c & 15)];
    }
    if (i < 2 * 16 * 48) {
        int c   = i % 48;
        int cc  = (i / 48) & 15;
        int dir = i / (48 * 16);
        const float* b = dir ? b_b : b_f;
        g_b1p3[i] = b[G3 + (c >> 4) * UU + cc * 16 + (c & 15)];
    }
}

// ---------------- phase 1: xp[m,n] = sum_k x[m,k]*W[k,n] + b0[n] -----------
// M=51200, K=311, N=768.  128x128x8 tile, 256 thr, 8x8 per-thread (f32x2),
// double-buffered smem with register prefetch (no fill bubble).
#define NKT 39   // ceil(311/8)

__global__ __launch_bounds__(256) void proj_kernel(
    const float* __restrict__ x,
    const float* __restrict__ k_f, const float* __restrict__ b_f,
    const float* __restrict__ k_b, const float* __restrict__ b_b)
{
    __shared__ float As[2][8 * 132];
    __shared__ float Bs[2][8 * 132];

    const int dir = blockIdx.z;
    const float* W    = dir ? k_b : k_f;
    const float* bias = dir ? b_b : b_f;       // row 0 = input bias
    float* xp = g_xp[dir];

    const int m0 = blockIdx.y * 128;
    const int n0 = blockIdx.x * 128;
    const int tid = threadIdx.x;
    const int tx = tid & 15;
    const int ty = tid >> 4;

    const int lxm = tid >> 1;            // 0..127
    const int lxk = (tid & 1) * 4;       // 0 or 4
    const int lbk = tid >> 5;            // 0..7
    const int lbn = (tid & 31) * 4;      // 0..124

    float  xa[4];
    float4 wb;

    // tile loader (into registers)
    auto load_tile = [&](int k0) {
#pragma unroll
        for (int j = 0; j < 4; j++) {
            int k = k0 + lxk + j;
            xa[j] = (k < DD) ? __ldg(&x[(size_t)(m0 + lxm) * DD + k]) : 0.0f;
        }
        if (k0 + lbk < DD)
            wb = *(const float4*)&W[(size_t)(k0 + lbk) * G3 + n0 + lbn];
        else
            wb = make_float4(0.f, 0.f, 0.f, 0.f);
    };

    u64 acc2[8][4];
#pragma unroll
    for (int i = 0; i < 8; i++)
#pragma unroll
        for (int j = 0; j < 4; j++) acc2[i][j] = 0ull;

    // prologue: tile 0 -> buf 0
    load_tile(0);
#pragma unroll
    for (int j = 0; j < 4; j++) As[0][(lxk + j) * 132 + lxm] = xa[j];
    *(float4*)&Bs[0][lbk * 132 + lbn] = wb;
    __syncthreads();

    for (int tIdx = 0; tIdx < NKT; tIdx++) {
        const int cur = tIdx & 1;
        if (tIdx + 1 < NKT) load_tile((tIdx + 1) * 8);   // prefetch (in flight)

#pragma unroll
        for (int kk = 0; kk < 8; kk++) {
            float4 a0 = *(float4*)&As[cur][kk * 132 + ty * 4];
            float4 a1 = *(float4*)&As[cur][kk * 132 + 64 + ty * 4];
            const u64* bp0 = (const u64*)&Bs[cur][kk * 132 + tx * 4];
            const u64* bp1 = (const u64*)&Bs[cur][kk * 132 + 64 + tx * 4];
            u64 bv[4] = {bp0[0], bp0[1], bp1[0], bp1[1]};
            float av[8] = {a0.x, a0.y, a0.z, a0.w, a1.x, a1.y, a1.z, a1.w};
#pragma unroll
            for (int i = 0; i < 8; i++) {
                u64 asp = splat2(av[i]);
#pragma unroll
                for (int j = 0; j < 4; j++) ffma2(acc2[i][j], asp, bv[j]);
            }
        }

        if (tIdx + 1 < NKT) {
            __syncthreads();
#pragma unroll
            for (int j = 0; j < 4; j++)
                As[cur ^ 1][(lxk + j) * 132 + lxm] = xa[j];
            *(float4*)&Bs[cur ^ 1][lbk * 132 + lbn] = wb;
            __syncthreads();
        }
    }

#pragma unroll
    for (int i = 0; i < 8; i++) {
        int row = m0 + ((i < 4) ? (ty * 4 + i) : (64 + ty * 4 + i - 4));
        float* o = &xp[(size_t)row * G3 + n0];
#pragma unroll
        for (int jh = 0; jh < 2; jh++) {
            int c0 = jh * 64 + tx * 4;
            float4 v;
            v.x = lo2(acc2[i][jh * 2 + 0]) + __ldg(&bias[n0 + c0 + 0]);
            v.y = hi2(acc2[i][jh * 2 + 0]) + __ldg(&bias[n0 + c0 + 1]);
            v.z = lo2(acc2[i][jh * 2 + 1]) + __ldg(&bias[n0 + c0 + 2]);
            v.w = hi2(acc2[i][jh * 2 + 1]) + __ldg(&bias[n0 + c0 + 3]);
            *(float4*)&o[c0] = v;
        }
    }
}

// ---------------- phase 2: one kernel per timestep, 2 CTAs/SM --------------
// grid = 256: blockIdx.x = dir*128 + bg*16 + cc
//   dir: direction, bg: batch group (32 rows), cc: 16-unit chunk.
// 256 threads. smem 90 KB -> 2 CTAs co-resident per SM (16 warps/SM):
// the two CTAs overlap each other's fills/gates against the shared fma pipe.
// GEMM 32x48x256, k-paired f32x2, col-major w, warp tile 16 rows x 12 cols.
#define KSW 260
#define SC_SMEM_FLOATS (48 * KSW + 32 * KSW + 32 * 52 + 48 + 32)
#define SC_SMEM_BYTES  (SC_SMEM_FLOATS * 4)

__global__ __launch_bounds__(256) void scan_step16_kernel(int s)
{
    extern __shared__ float sm[];
    float* rs2  = sm;                     // [48][260] rk slice, col-major
    float* hs   = rs2 + 48 * KSW;         // [32][260] h_prev
    float* recs = hs + 32 * KSW;          // [32][52]  rec + b1
    float* b1s  = recs + 32 * 52;         // [48]
    int*   mkv  = (int*)(b1s + 48);       // [32]

    const int tid = threadIdx.x;
    const int cc  = blockIdx.x & 15;
    const int bg  = (blockIdx.x >> 4) & 7;
    const int dir = blockIdx.x >> 7;
    const int u0  = cc * 16;
    const int b0  = bg * 32;

    const int t  = dir ? (TT - 1 - s) : s;
    const int tp = dir ? (t + 1) : (t - 1);    // valid only when s > 0

    float*       y  = g_y[dir];
    const float* xp = g_xp[dir];

    // ---- fill smem ----
    {   // rk slice: 48 cols x 64 quads from packed layout (L2-hot)
        const float4* src =
            (const float4*)(g_rkp3 + (size_t)(dir * 16 + cc) * 48 * 256);
#pragma unroll
        for (int i = 0; i < 12; i++) {
            int idx = tid + 256 * i;
            int c = idx >> 6, q = idx & 63;
            *(float4*)&rs2[c * KSW + 4 * q] = src[idx];
        }
    }
    if (tid < 48) b1s[tid] = g_b1p3[(dir * 16 + cc) * 48 + tid];
    if (tid >= 64 && tid < 96) mkv[tid - 64] = g_mask[(b0 + tid - 64) * TT + t];

    if (s == 0) {
        for (int i = tid; i < 32 * KSW; i += 256) hs[i] = 0.0f;
    } else {
#pragma unroll
        for (int i = 0; i < 8; i++) {            // 32 rows x 64 float4
            int idx = tid + 256 * i;
            int row = idx >> 6, q = idx & 63;
            *(float4*)&hs[row * KSW + 4 * q] =
                *(const float4*)&y[((size_t)(b0 + row) * TT + tp) * UU + 4 * q];
        }
    }
    __syncthreads();

    // ---- GEMM 32x48x256, k-paired f32x2 ----
    // warp w: rows (w&1)*16+[0,16), cols (w>>1)*12+[0,12)
    // lane: row = rg*16 + (lane&15); ch = lane>>4 -> cols +ch*6+[0,6)
    const int warp = tid >> 5, lane = tid & 31;
    const int rg = warp & 1, cg = warp >> 1;
    const int row = rg * 16 + (lane & 15);
    const int cb  = cg * 12 + (lane >> 4) * 6;

    const float* hp    = &hs[row * KSW];
    const float* wbase = &rs2[cb * KSW];

    u64 acc[6];
#pragma unroll
    for (int j = 0; j < 6; j++) acc[j] = 0ull;

#pragma unroll 4
    for (int k0 = 0; k0 < 256; k0 += 4) {
        ulonglong2 h2 = *(const ulonglong2*)(hp + k0);
#pragma unroll
        for (int j = 0; j < 6; j++) {
            ulonglong2 w2 = *(const ulonglong2*)(wbase + j * KSW + k0);
            ffma2(acc[j], h2.x, w2.x);
            ffma2(acc[j], h2.y, w2.y);
        }
    }

    // reduce k-pairs, + recurrent bias
#pragma unroll
    for (int j = 0; j < 6; j++)
        recs[row * 52 + cb + j] = lo2(acc[j]) + hi2(acc[j]) + b1s[cb + j];
    __syncthreads();

    // ---- gates: 2 (row, unit) items per thread ----
#pragma unroll
    for (int it = 0; it < 2; it++) {
        int i = tid + 256 * it;          // 0..511
        int r = i >> 4, u = i & 15;
        float rz = recs[r * 52 + u];
        float rr = recs[r * 52 + 16 + u];
        float rh = recs[r * 52 + 32 + u];
        size_t base = ((size_t)(b0 + r) * TT + t) * G3 + u0 + u;
        float xz = xp[base];
        float xr = xp[base + UU];
        float xh = xp[base + 2 * UU];
        float hpv = hs[r * KSW + u0 + u];
        float z  = sigmoidf_(xz + rz);
        float rr2 = sigmoidf_(xr + rr);
        float hh = tanhf(xh + rr2 * rh);
        float hn = z * hpv + (1.0f - z) * hh;
        if (!mkv[r]) hn = hpv;
        y[((size_t)(b0 + r) * TT + t) * UU + u0 + u] = hn;
    }
}

// ---------------- phase 3: dense + softmax ---------------------------------
__global__ __launch_bounds__(256) void dense_kernel(
    const float* __restrict__ w_d, const float* __restrict__ b_d,
    float* __restrict__ out)
{
    __shared__ float ws[2 * UU * NOUT];   // 512*19
    __shared__ float bs[NOUT];
    for (int i = threadIdx.x; i < 2 * UU * NOUT; i += 256) ws[i] = w_d[i];
    if (threadIdx.x < NOUT) bs[threadIdx.x] = b_d[threadIdx.x];
    __syncthreads();

    int warp = threadIdx.x >> 5, lane = threadIdx.x & 31;
    int row = blockIdx.x * 8 + warp;               // 6400 * 8 = 51200 exact
    const float* hf = g_y[0] + (size_t)row * UU;
    const float* hb = g_y[1] + (size_t)row * UU;

    float acc[NOUT];
#pragma unroll
    for (int o = 0; o < NOUT; o++) acc[o] = 0.0f;

    for (int j = lane; j < UU; j += 32) {
        float a = hf[j];
        const float* w = &ws[j * NOUT];
#pragma unroll
        for (int o = 0; o < NOUT; o++) acc[o] += a * w[o];
        float b = hb[j];
        const float* w2 = &ws[(UU + j) * NOUT];
#pragma unroll
        for (int o = 0; o < NOUT; o++) acc[o] += b * w2[o];
    }
#pragma unroll
    for (int off = 16; off > 0; off >>= 1)
#pragma unroll
        for (int o = 0; o < NOUT; o++)
            acc[o] += __shfl_xor_sync(0xffffffffu, acc[o], off);

#pragma unroll
    for (int o = 0; o < NOUT; o++) acc[o] += bs[o];
    float m = acc[0];
#pragma unroll
    for (int o = 1; o < NOUT; o++) m = fmaxf(m, acc[o]);
    float sum = 0.0f;
#pragma unroll
    for (int o = 0; o < NOUT; o++) { acc[o] = expf(acc[o] - m); sum += acc[o]; }
    float inv = 1.0f / sum;

    if (lane < NOUT) {
        float v = 0.0f;
#pragma unroll
        for (int o = 0; o < NOUT; o++) if (lane == o) v = acc[o];
        out[(size_t)row * NOUT + lane] = v * inv;
    }
}

// ---------------- launch ----------------------------------------------------
extern "C" void kernel_launch(void* const* d_in, const int* in_sizes, int n_in,
                              void* d_out, int out_size)
{
    const float* x    = (const float*)d_in[0];
    const float* k_f  = (const float*)d_in[1];
    const float* rk_f = (const float*)d_in[2];
    const float* b_f  = (const float*)d_in[3];
    const float* k_b  = (const float*)d_in[4];
    const float* rk_b = (const float*)d_in[5];
    const float* b_b  = (const float*)d_in[6];
    const float* w_d  = (const float*)d_in[7];
    const float* b_d  = (const float*)d_in[8];
    float* out = (float*)d_out;

    // mask + weight pack + input projections
    mask_kernel<<<BT / 8, 256>>>(x);
    pack_kernel<<<(2 * 16 * 48 * 256) / 256, 256>>>(rk_f, rk_b, b_f, b_b);
    dim3 pg(G3 / 128, BT / 128, 2);
    proj_kernel<<<pg, 256>>>(x, k_f, b_f, k_b, b_b);

    // recurrent scan: one plain launch per timestep, 256 CTAs (2 per SM)
    cudaFuncSetAttribute(scan_step16_kernel,
                         cudaFuncAttributeMaxDynamicSharedMemorySize,
                         SC_SMEM_BYTES);
    for (int s = 0; s < TT; s++)
        scan_step16_kernel<<<256, 256, SC_SMEM_BYTES>>>(s);

    // dense + softmax
    dense_kernel<<<BT / 8, 256>>>(w_d, b_d, out);
}

// round 10
// speedup vs baseline: 1.9211x; 1.2038x over previous
#include <cuda_runtime.h>
#include <cuda_bf16.h>
#include <cstdint>
#include <math.h>

// Problem dims
#define BB   256
#define TT   200
#define DD   311
#define UU   256
#define G3   768          // 3*U
#define NOUT 19
#define BT   (BB*TT)      // 51200

typedef unsigned long long u64;

// ---------------- packed f32x2 helpers (Blackwell PTX) ---------------------
__device__ __forceinline__ u64 splat2(float v) {
    u64 r; unsigned u = __float_as_uint(v);
    asm("mov.b64 %0, {%1, %1};" : "=l"(r) : "r"(u));
    return r;
}
__device__ __forceinline__ void ffma2(u64& d, u64 a, u64 b) {
    asm("fma.rn.f32x2 %0, %1, %2, %0;" : "+l"(d) : "l"(a), "l"(b));
}
__device__ __forceinline__ float lo2(u64 v) {
    return __uint_as_float((unsigned)(v & 0xffffffffull));
}
__device__ __forceinline__ float hi2(u64 v) {
    return __uint_as_float((unsigned)(v >> 32));
}

// ---------------- cp.async helpers -----------------------------------------
__device__ __forceinline__ unsigned smem_u32(const void* p) {
    unsigned r;
    asm("{ .reg .u64 t; cvta.to.shared.u64 t, %1; cvt.u32.u64 %0, t; }"
        : "=r"(r) : "l"(p));
    return r;
}
#define CP16(dst, src) \
    asm volatile("cp.async.cg.shared.global [%0], [%1], 16;" :: "r"(dst), "l"(src))
#define CP4(dst, src) \
    asm volatile("cp.async.ca.shared.global [%0], [%1], 4;" :: "r"(dst), "l"(src))
#define CPCOMMIT() asm volatile("cp.async.commit_group;")
#define CPWAIT1()  asm volatile("cp.async.wait_group 1;" ::: "memory")

// ---------------- scratch (device globals; no cudaMalloc allowed) ----------
__device__ float g_xp[2][(size_t)BT * G3];   // input projections, per direction
__device__ float g_y [2][(size_t)BT * UU];   // hidden sequences
__device__ int   g_mask[BT];
__device__ float g_rkp2[2 * 8 * 96 * 256];   // rk col-major [dir][cc][col][k]
__device__ float g_b1p[2 * 8 * 96];          // recurrent bias per (dir, cc)
__device__ int   g_flags[2 * 8 * TT];        // [dir][bg][step] arrival counters

__device__ __forceinline__ float sigmoidf_(float v) {
    return 1.0f / (1.0f + expf(-v));
}

// ---------------- mask: mask[b,t] = any(x[b,t,:] != 0) ---------------------
__global__ __launch_bounds__(256) void mask_kernel(const float* __restrict__ x) {
    int warp = (blockIdx.x * blockDim.x + threadIdx.x) >> 5;
    int lane = threadIdx.x & 31;
    if (warp >= BT) return;
    const float* row = x + (size_t)warp * DD;
    int any = 0;
    for (int i = lane; i < DD; i += 32) any |= (row[i] != 0.0f);
    unsigned b = __ballot_sync(0xffffffffu, any);
    if (lane == 0) g_mask[warp] = (b != 0u);
}

// ---------------- weight pre-pack: col-major per (dir, unit-chunk) ---------
// local col c in [0,96): global col (c/32)*256 + cc*32 + (c%32); k contiguous.
__global__ __launch_bounds__(256) void pack_kernel(
    const float* __restrict__ rk_f, const float* __restrict__ rk_b,
    const float* __restrict__ b_f,  const float* __restrict__ b_b)
{
    int i = blockIdx.x * blockDim.x + threadIdx.x;
    const int total = 2 * 8 * 96 * 256;
    if (i < total) {
        int k     = i & 255;
        int rest  = i >> 8;
        int c     = rest % 96;
        int slice = rest / 96;          // 0..15
        int cc    = slice & 7;
        int dir   = slice >> 3;
        const float* rk = dir ? rk_b : rk_f;
        g_rkp2[i] = rk[(size_t)k * G3 + (c >> 5) * UU + cc * 32 + (c & 31)];
    }
    if (i < 2 * 8 * 96) {
        int c   = i % 96;
        int cc  = (i / 96) & 7;
        int dir = i / (96 * 8);
        const float* b = dir ? b_b : b_f;
        g_b1p[i] = b[G3 + (c >> 5) * UU + cc * 32 + (c & 31)];
    }
}

// ---------------- flag clear (graph replays need fresh flags) --------------
__global__ void clear_flags_kernel() {
    int i = blockIdx.x * blockDim.x + threadIdx.x;
    if (i < 2 * 8 * TT) g_flags[i] = 0;
}

// ---------------- phase 1: xp[m,n] = sum_k x[m,k]*W[k,n] + b0[n] -----------
// M=51200, K=311, N=768.  128x128x8 tile, 256 thr, 8x8 per-thread (f32x2),
// double-buffered smem with register prefetch.
#define NKT 39   // ceil(311/8)

__global__ __launch_bounds__(256) void proj_kernel(
    const float* __restrict__ x,
    const float* __restrict__ k_f, const float* __restrict__ b_f,
    const float* __restrict__ k_b, const float* __restrict__ b_b)
{
    __shared__ float As[2][8 * 132];
    __shared__ float Bs[2][8 * 132];

    const int dir = blockIdx.z;
    const float* W    = dir ? k_b : k_f;
    const float* bias = dir ? b_b : b_f;       // row 0 = input bias
    float* xp = g_xp[dir];

    const int m0 = blockIdx.y * 128;
    const int n0 = blockIdx.x * 128;
    const int tid = threadIdx.x;
    const int tx = tid & 15;
    const int ty = tid >> 4;

    const int lxm = tid >> 1;            // 0..127
    const int lxk = (tid & 1) * 4;       // 0 or 4
    const int lbk = tid >> 5;            // 0..7
    const int lbn = (tid & 31) * 4;      // 0..124

    float  xa[4];
    float4 wb;

    auto load_tile = [&](int k0) {
#pragma unroll
        for (int j = 0; j < 4; j++) {
            int k = k0 + lxk + j;
            xa[j] = (k < DD) ? __ldg(&x[(size_t)(m0 + lxm) * DD + k]) : 0.0f;
        }
        if (k0 + lbk < DD)
            wb = *(const float4*)&W[(size_t)(k0 + lbk) * G3 + n0 + lbn];
        else
            wb = make_float4(0.f, 0.f, 0.f, 0.f);
    };

    u64 acc2[8][4];
#pragma unroll
    for (int i = 0; i < 8; i++)
#pragma unroll
        for (int j = 0; j < 4; j++) acc2[i][j] = 0ull;

    load_tile(0);
#pragma unroll
    for (int j = 0; j < 4; j++) As[0][(lxk + j) * 132 + lxm] = xa[j];
    *(float4*)&Bs[0][lbk * 132 + lbn] = wb;
    __syncthreads();

    for (int tIdx = 0; tIdx < NKT; tIdx++) {
        const int cur = tIdx & 1;
        if (tIdx + 1 < NKT) load_tile((tIdx + 1) * 8);

#pragma unroll
        for (int kk = 0; kk < 8; kk++) {
            float4 a0 = *(float4*)&As[cur][kk * 132 + ty * 4];
            float4 a1 = *(float4*)&As[cur][kk * 132 + 64 + ty * 4];
            const u64* bp0 = (const u64*)&Bs[cur][kk * 132 + tx * 4];
            const u64* bp1 = (const u64*)&Bs[cur][kk * 132 + 64 + tx * 4];
            u64 bv[4] = {bp0[0], bp0[1], bp1[0], bp1[1]};
            float av[8] = {a0.x, a0.y, a0.z, a0.w, a1.x, a1.y, a1.z, a1.w};
#pragma unroll
            for (int i = 0; i < 8; i++) {
                u64 asp = splat2(av[i]);
#pragma unroll
                for (int j = 0; j < 4; j++) ffma2(acc2[i][j], asp, bv[j]);
            }
        }

        if (tIdx + 1 < NKT) {
            __syncthreads();
#pragma unroll
            for (int j = 0; j < 4; j++)
                As[cur ^ 1][(lxk + j) * 132 + lxm] = xa[j];
            *(float4*)&Bs[cur ^ 1][lbk * 132 + lbn] = wb;
            __syncthreads();
        }
    }

#pragma unroll
    for (int i = 0; i < 8; i++) {
        int row = m0 + ((i < 4) ? (ty * 4 + i) : (64 + ty * 4 + i - 4));
        float* o = &xp[(size_t)row * G3 + n0];
#pragma unroll
        for (int jh = 0; jh < 2; jh++) {
            int c0 = jh * 64 + tx * 4;
            float4 v;
            v.x = lo2(acc2[i][jh * 2 + 0]) + __ldg(&bias[n0 + c0 + 0]);
            v.y = hi2(acc2[i][jh * 2 + 0]) + __ldg(&bias[n0 + c0 + 1]);
            v.z = lo2(acc2[i][jh * 2 + 1]) + __ldg(&bias[n0 + c0 + 2]);
            v.w = hi2(acc2[i][jh * 2 + 1]) + __ldg(&bias[n0 + c0 + 3]);
            *(float4*)&o[c0] = v;
        }
    }
}

// ---------------- phase 2: persistent scan (single wave, flag barriers) ----
// grid = 128 CTAs, 256 thr, 171 KB smem -> exactly 1 CTA/SM, single wave
// (128 <= 148), so the per-(dir,bg) 8-CTA flag barrier cannot deadlock.
// blockIdx.x = dir*64 + bg*8 + cc. rk slice pinned in smem for all 200 steps.
// Next-step xp/mask prefetched via cp.async double buffer during the GEMM.
#define KS 260
#define SC2_FLOATS (96 * KS + 32 * KS + 32 * 100 + 2 * 32 * 96 + 96 + 64)
#define SC2_BYTES  (SC2_FLOATS * 4)

__global__ __launch_bounds__(256) void scan_persist2()
{
    extern __shared__ float sm[];
    float* rs2  = sm;                       // [96][260] rk slice, col-major
    float* hs   = rs2 + 96 * KS;            // [32][260] h_prev
    float* recs = hs + 32 * KS;             // [32][100] rec + b1
    float* xpb  = recs + 32 * 100;          // [2][32][96] xp double buffer
    float* b1s  = xpb + 2 * 32 * 96;        // [96]
    int*   mkv  = (int*)(b1s + 96);         // [2][32]

    const int tid = threadIdx.x;
    const int cc  = blockIdx.x & 7;
    const int bg  = (blockIdx.x >> 3) & 7;
    const int dir = blockIdx.x >> 6;
    const int u0  = cc * 32;
    const int b0  = bg * 32;

    float*       y  = g_y[dir];
    const float* xp = g_xp[dir];
    int* flags = g_flags + (dir * 8 + bg) * TT;
    volatile int* vflags = (volatile int*)flags;

    const unsigned xpb_a = smem_u32(xpb);
    const unsigned mkv_a = smem_u32(mkv);

    // ---- one-time fills ----
    {   // rk slice: packed contiguous [96][256] -> smem stride-260 col-major
        const float4* src =
            (const float4*)(g_rkp2 + (size_t)(dir * 8 + cc) * 96 * 256);
#pragma unroll
        for (int i = 0; i < 24; i++) {
            int idx = tid + 256 * i;        // 96*64 = 6144 quads
            int c = idx >> 6, q = idx & 63;
            *(float4*)&rs2[c * KS + 4 * q] = src[idx];
        }
    }
    if (tid < 96) b1s[tid] = g_b1p[(dir * 8 + cc) * 96 + tid];
    for (int i = tid; i < 32 * KS; i += 256) hs[i] = 0.0f;    // h0 = 0

    // xp/mask prefetch for a given t into buffer buf
    auto prefetch = [&](int tn, int buf) {
        unsigned dbase = xpb_a + (unsigned)(buf * 3072) * 4u;
#pragma unroll
        for (int it = 0; it < 3; it++) {
            int j = tid + 256 * it;         // 0..767, 16B each
            int p = j >> 3, o = j & 7;
            int row = p / 3, seg = p - 3 * row;
            const float* src =
                xp + ((size_t)(b0 + row) * TT + tn) * G3 + seg * UU + u0 + o * 4;
            CP16(dbase + (unsigned)(row * 96 + seg * 32 + o * 4) * 4u, src);
        }
        if (tid < 32)
            CP4(mkv_a + (unsigned)(buf * 32 + tid) * 4u,
                &g_mask[(b0 + tid) * TT + tn]);
    };

    prefetch(dir ? (TT - 1) : 0, 0);
    CPCOMMIT();
    __syncthreads();

    const int rt = tid & 15;          // rows {rt, rt+16}
    const int ct = tid >> 4;          // cols 6ct..6ct+5

    const float* h0p = &hs[rt * KS];
    const float* h1p = &hs[(rt + 16) * KS];
    const float* wp  = &rs2[(6 * ct) * KS];

    for (int s = 0; s < TT; s++) {
        const int t = dir ? (TT - 1 - s) : s;

        // prefetch next step's xp/mask (independent of peer CTAs)
        if (s + 1 < TT) prefetch(dir ? (t - 1) : (t + 1), (s + 1) & 1);
        CPCOMMIT();                       // empty group on last step is fine

        if (s > 0) {
            const int tp = dir ? (t + 1) : (t - 1);
            if (tid == 0) {
                while (vflags[s - 1] < 8) __nanosleep(40);
            }
            __syncthreads();
            __threadfence();              // acquire side
#pragma unroll
            for (int i = 0; i < 8; i++) { // 32 rows x 64 float4
                int idx = tid + 256 * i;
                int row = idx >> 6, q = idx & 63;
                *(float4*)&hs[row * KS + 4 * q] =
                    *(const float4*)&y[((size_t)(b0 + row) * TT + tp) * UU + 4 * q];
            }
        }
        __syncthreads();

        // ---- GEMM 32x96x256, k-paired f32x2 ----
        u64 acc[2][6];
#pragma unroll
        for (int i = 0; i < 2; i++)
#pragma unroll
            for (int j = 0; j < 6; j++) acc[i][j] = 0ull;

#pragma unroll 2
        for (int k0 = 0; k0 < 256; k0 += 4) {
            ulonglong2 ha = *(const ulonglong2*)(h0p + k0);
            ulonglong2 hb = *(const ulonglong2*)(h1p + k0);
#pragma unroll
            for (int j = 0; j < 6; j++) {
                ulonglong2 w = *(const ulonglong2*)(wp + j * KS + k0);
                ffma2(acc[0][j], ha.x, w.x);
                ffma2(acc[0][j], ha.y, w.y);
                ffma2(acc[1][j], hb.x, w.x);
                ffma2(acc[1][j], hb.y, w.y);
            }
        }

#pragma unroll
        for (int i = 0; i < 2; i++) {
            int row = rt + 16 * i;
#pragma unroll
            for (int j = 0; j < 6; j++)
                recs[row * 100 + 6 * ct + j] =
                    lo2(acc[i][j]) + hi2(acc[i][j]) + b1s[6 * ct + j];
        }
        CPWAIT1();                        // xp buf[s&1] landed
        __syncthreads();                  // publish recs + cp.async data

        // ---- gates: 4 (row, unit) items per thread ----
        const float* xb = &xpb[(s & 1) * 3072];
        const int*   mk = &mkv[(s & 1) * 32];
#pragma unroll
        for (int it = 0; it < 4; it++) {
            int i = tid + 256 * it;
            int r = i >> 5, u = i & 31;
            float rz = recs[r * 100 + u];
            float rr = recs[r * 100 + 32 + u];
            float rh = recs[r * 100 + 64 + u];
            const float* xr0 = &xb[r * 96];
            float xz = xr0[u], xr = xr0[32 + u], xh = xr0[64 + u];
            float hpv = hs[r * KS + u0 + u];
            float z  = sigmoidf_(xz + rz);
            float rg = sigmoidf_(xr + rr);
            float hh = tanhf(xh + rg * rh);
            float hn = z * hpv + (1.0f - z) * hh;
            if (!mk[r]) hn = hpv;
            y[((size_t)(b0 + r) * TT + t) * UU + u0 + u] = hn;
        }

        __syncthreads();                  // all y stores issued
        if (tid == 0) {
            __threadfence();              // release side
            atomicAdd(&flags[s], 1);
        }
    }
}

// ---------------- phase 3: dense + softmax ---------------------------------
__global__ __launch_bounds__(256) void dense_kernel(
    const float* __restrict__ w_d, const float* __restrict__ b_d,
    float* __restrict__ out)
{
    __shared__ float ws[2 * UU * NOUT];   // 512*19
    __shared__ float bs[NOUT];
    for (int i = threadIdx.x; i < 2 * UU * NOUT; i += 256) ws[i] = w_d[i];
    if (threadIdx.x < NOUT) bs[threadIdx.x] = b_d[threadIdx.x];
    __syncthreads();

    int warp = threadIdx.x >> 5, lane = threadIdx.x & 31;
    int row = blockIdx.x * 8 + warp;               // 6400 * 8 = 51200 exact
    const float* hf = g_y[0] + (size_t)row * UU;
    const float* hb = g_y[1] + (size_t)row * UU;

    float acc[NOUT];
#pragma unroll
    for (int o = 0; o < NOUT; o++) acc[o] = 0.0f;

    for (int j = lane; j < UU; j += 32) {
        float a = hf[j];
        const float* w = &ws[j * NOUT];
#pragma unroll
        for (int o = 0; o < NOUT; o++) acc[o] += a * w[o];
        float b = hb[j];
        const float* w2 = &ws[(UU + j) * NOUT];
#pragma unroll
        for (int o = 0; o < NOUT; o++) acc[o] += b * w2[o];
    }
#pragma unroll
    for (int off = 16; off > 0; off >>= 1)
#pragma unroll
        for (int o = 0; o < NOUT; o++)
            acc[o] += __shfl_xor_sync(0xffffffffu, acc[o], off);

#pragma unroll
    for (int o = 0; o < NOUT; o++) acc[o] += bs[o];
    float m = acc[0];
#pragma unroll
    for (int o = 1; o < NOUT; o++) m = fmaxf(m, acc[o]);
    float sum = 0.0f;
#pragma unroll
    for (int o = 0; o < NOUT; o++) { acc[o] = expf(acc[o] - m); sum += acc[o]; }
    float inv = 1.0f / sum;

    if (lane < NOUT) {
        float v = 0.0f;
#pragma unroll
        for (int o = 0; o < NOUT; o++) if (lane == o) v = acc[o];
        out[(size_t)row * NOUT + lane] = v * inv;
    }
}

// ---------------- launch ----------------------------------------------------
extern "C" void kernel_launch(void* const* d_in, const int* in_sizes, int n_in,
                              void* d_out, int out_size)
{
    const float* x    = (const float*)d_in[0];
    const float* k_f  = (const float*)d_in[1];
    const float* rk_f = (const float*)d_in[2];
    const float* b_f  = (const float*)d_in[3];
    const float* k_b  = (const float*)d_in[4];
    const float* rk_b = (const float*)d_in[5];
    const float* b_b  = (const float*)d_in[6];
    const float* w_d  = (const float*)d_in[7];
    const float* b_d  = (const float*)d_in[8];
    float* out = (float*)d_out;

    // mask + weight pack + flag clear + input projections
    mask_kernel<<<BT / 8, 256>>>(x);
    pack_kernel<<<(2 * 8 * 96 * 256) / 256, 256>>>(rk_f, rk_b, b_f, b_b);
    clear_flags_kernel<<<13, 256>>>();
    dim3 pg(G3 / 128, BT / 128, 2);
    proj_kernel<<<pg, 256>>>(x, k_f, b_f, k_b, b_b);

    // persistent scan: 128 CTAs, 1/SM single wave, 200 steps in one launch
    cudaFuncSetAttribute(scan_persist2,
                         cudaFuncAttributeMaxDynamicSharedMemorySize,
                         SC2_BYTES);
    scan_persist2<<<128, 256, SC2_BYTES>>>();

    // dense + softmax
    dense_kernel<<<BT / 8, 256>>>(w_d, b_d, out);
}